// round 8
// baseline (speedup 1.0000x reference)
#include <cuda_runtime.h>
#include <math.h>
#include <stdint.h>

#define NTOK 8192
#define DIN  1024
#define NEXP 8
#define HID  4096
#define OUTD 1024
#define GH   4096

// ---------------- scratch ----------------
__device__ float g_h1 [(size_t)NTOK * GH];
__device__ float g_h2 [(size_t)NTOK * DIN];
__device__ float g_hid [(size_t)NEXP * NTOK * HID];
__device__ float g_pout[(size_t)NEXP * NTOK * OUTD];
__device__ int   g_cnt [NEXP];
__device__ int   g_list[NEXP * NTOK];
__device__ int   g_slot[NTOK * 2];
__device__ float g_wt  [NTOK * 2];

__device__ __forceinline__ uint32_t cvta_s(const void* p) {
    uint32_t a;
    asm("{ .reg .u64 t; cvta.to.shared.u64 t, %1; cvt.u32.u64 %0, t; }" : "=r"(a) : "l"(p));
    return a;
}
__device__ __forceinline__ void mma_bf16(float* c, const uint32_t* a, uint32_t b0, uint32_t b1) {
    asm volatile(
        "mma.sync.aligned.m16n8k16.row.col.f32.bf16.bf16.f32 "
        "{%0,%1,%2,%3}, {%4,%5,%6,%7}, {%8,%9}, {%0,%1,%2,%3};\n"
        : "+f"(c[0]), "+f"(c[1]), "+f"(c[2]), "+f"(c[3])
        : "r"(a[0]), "r"(a[1]), "r"(a[2]), "r"(a[3]), "r"(b0), "r"(b1));
}
#define LDSM4(R, addr) \
    asm volatile("ldmatrix.sync.aligned.m8n8.x4.shared.b16 {%0,%1,%2,%3}, [%4];" \
        : "=r"((R)[0]), "=r"((R)[1]), "=r"((R)[2]), "=r"((R)[3]) : "r"(addr))
#define LDSM4T(R, addr) \
    asm volatile("ldmatrix.sync.aligned.m8n8.x4.trans.shared.b16 {%0,%1,%2,%3}, [%4];" \
        : "=r"((R)[0]), "=r"((R)[1]), "=r"((R)[2]), "=r"((R)[3]) : "r"(addr))

// pack pair (x -> low half, y -> high half) as bf16x2 with rn rounding
__device__ __forceinline__ uint32_t bfpack(float x, float y) {
    uint32_t r;
    asm("cvt.rn.satfinite.bf16x2.f32 %0, %1, %2;" : "=r"(r) : "f"(y), "f"(x));
    return r;
}
__device__ __forceinline__ void sub_bf(float& x, float& y, uint32_t h) {
    x -= __uint_as_float(h << 16);
    y -= __uint_as_float(h & 0xFFFF0000u);
}

// SMEM planes (bytes): A [128 m][24 bf16] stride 48B; B [16 k][136 bf16] stride 272B
#define A_PLB (128 * 48)     // 6144
#define B_PLB (16 * 272)     // 4352
// stage bytes = NS*(A_PLB + B_PLB); two stages
#define SMEM_MAX (2 * 3 * (A_PLB + B_PLB))   // 62976 (NS=3 case)

// ---------------- reset ----------------
__global__ void reset_kernel() {
    if (threadIdx.x < NEXP) g_cnt[threadIdx.x] = 0;
}

// ---------------- NS-split bf16 GEMM: C = (A @ B + bias)[relu], B row-major [K,N] ----------------
// NS=2: 3 MMAs/k16 (experts). NS=3: 6 MMAs/k16 (gates, err ~2^-23).
// 256 threads, 8 warps, warp tile 64x32 (2m x 4n), CTA tile 128x128, BK=16, 2-stage smem.
template<int NS>
__global__ __launch_bounds__(256) void gemm_tc(
    const float* __restrict__ A, size_t sAe,
    const float* __restrict__ B, size_t sBe,
    const float* __restrict__ bias, size_t sBiasE,
    float* __restrict__ C, size_t sCe,
    int K, int N, int doRelu,
    const int* __restrict__ list, const int* __restrict__ cntArr)
{
    const int STAGEB = NS * (A_PLB + B_PLB);
    const int NMMA = (NS == 2) ? 3 : 6;
    // pass pairs (aPlane, bPlane)
    const int PA[6] = {0, 0, 1, 0, 2, 1};
    const int PB[6] = {0, 1, 0, 2, 0, 1};

    const int e   = blockIdx.z;
    const int cnt = cntArr ? cntArr[e] : (int)(gridDim.y * 128);
    const int m0  = blockIdx.y * 128;
    if (m0 >= cnt) return;
    const int n0  = blockIdx.x * 128;

    extern __shared__ char smem[];
    const uint32_t sbase = cvta_s(smem);

    const int tid  = threadIdx.x;
    const int wid  = tid >> 5;
    const int lane = tid & 31;
    const int wm0  = (wid >> 2) * 64;
    const int wn0  = (wid & 3) * 32;

    // producer indices
    int arow = m0 + (tid >> 1); if (arow > cnt - 1) arow = cnt - 1;
    if (list) arow = list[e * NTOK + arow];
    const int aks = (tid & 1) * 8;                 // k segment 0 or 8
    const float* Ap = A + sAe * e + (size_t)arow * K + aks;
    const int bk = tid >> 4;                       // 0..15
    const int bn = (tid & 15) * 8;                 // 0..120
    const float* Bp = B + sBe * e + (size_t)bk * N + n0 + bn;
    const uint32_t aoff = (uint32_t)((tid >> 1) * 48 + aks * 2);     // byte offset in A plane
    const uint32_t boff = (uint32_t)(bk * 272 + bn * 2);             // byte offset in B plane

    const int T = K >> 4;
    float4 pa0, pa1, pb0, pb1;

    auto load_regs = [&](int kt) {
        const float* ap = Ap + kt * 16;
        pa0 = *(const float4*)(ap);
        pa1 = *(const float4*)(ap + 4);
        const float* bp = Bp + (size_t)kt * 16 * N;
        pb0 = *(const float4*)(bp);
        pb1 = *(const float4*)(bp + 4);
    };
    auto split_sts = [&](int s) {
        float av[8] = {pa0.x, pa0.y, pa0.z, pa0.w, pa1.x, pa1.y, pa1.z, pa1.w};
        float bv[8] = {pb0.x, pb0.y, pb0.z, pb0.w, pb1.x, pb1.y, pb1.z, pb1.w};
        uint32_t PAq[3][4], PBq[3][4];
        #pragma unroll
        for (int j = 0; j < 4; j++) {
            float x = av[2 * j], y = av[2 * j + 1];
            PAq[0][j] = bfpack(x, y); sub_bf(x, y, PAq[0][j]);
            PAq[1][j] = bfpack(x, y);
            if (NS == 3) { sub_bf(x, y, PAq[1][j]); PAq[2][j] = bfpack(x, y); }
            float u = bv[2 * j], v = bv[2 * j + 1];
            PBq[0][j] = bfpack(u, v); sub_bf(u, v, PBq[0][j]);
            PBq[1][j] = bfpack(u, v);
            if (NS == 3) { sub_bf(u, v, PBq[1][j]); PBq[2][j] = bfpack(u, v); }
        }
        char* st = smem + s * STAGEB;
        #pragma unroll
        for (int pl = 0; pl < NS; pl++) {
            *(uint4*)(st + pl * A_PLB + aoff) =
                make_uint4(PAq[pl][0], PAq[pl][1], PAq[pl][2], PAq[pl][3]);
            *(uint4*)(st + NS * A_PLB + pl * B_PLB + boff) =
                make_uint4(PBq[pl][0], PBq[pl][1], PBq[pl][2], PBq[pl][3]);
        }
    };

    float acc[4][4][4];
    #pragma unroll
    for (int im = 0; im < 4; im++)
        #pragma unroll
        for (int jn = 0; jn < 4; jn++)
            #pragma unroll
            for (int q = 0; q < 4; q++) acc[im][jn][q] = 0.f;

    load_regs(0);
    split_sts(0);
    __syncthreads();

    // consumer ldmatrix base offsets (lane-dependent)
    const uint32_t aLdOff = (uint32_t)((wm0 + (lane & 15)) * 48 + (lane >> 4) * 16);
    const uint32_t bLdOff = (uint32_t)((lane & 15) * 272 + (wn0 + (lane >> 4) * 8) * 2);

    for (int kt = 0; kt < T; ++kt) {
        if (kt + 1 < T) load_regs(kt + 1);

        const uint32_t sb = sbase + (uint32_t)((kt & 1) * STAGEB);
        uint32_t aF[NS][4][4];    // plane, im, regs
        uint32_t bF[NS][2][4];    // plane, n-half (2 n8-tiles per x4), regs
        #pragma unroll
        for (int pl = 0; pl < NS; pl++) {
            #pragma unroll
            for (int im = 0; im < 4; im++)
                LDSM4(aF[pl][im], sb + pl * A_PLB + aLdOff + (uint32_t)(im * 16 * 48));
            #pragma unroll
            for (int nh = 0; nh < 2; nh++)
                LDSM4T(bF[pl][nh], sb + NS * A_PLB + pl * B_PLB + bLdOff + (uint32_t)(nh * 32));
        }
        #pragma unroll
        for (int ps = 0; ps < NMMA; ps++) {
            const int pa = PA[ps], pb = PB[ps];
            #pragma unroll
            for (int im = 0; im < 4; im++)
                #pragma unroll
                for (int jn = 0; jn < 4; jn++)
                    mma_bf16(acc[im][jn], aF[pa][im],
                             bF[pb][jn >> 1][(jn & 1) * 2],
                             bF[pb][jn >> 1][(jn & 1) * 2 + 1]);
        }

        if (kt + 1 < T) split_sts((kt + 1) & 1);
        __syncthreads();
    }

    // ---- epilogue: bias + relu + store ----
    const float* bp = bias + sBiasE * e + n0;
    float* Cbase = C + sCe * e;
    #pragma unroll
    for (int im = 0; im < 4; im++) {
        #pragma unroll
        for (int half = 0; half < 2; half++) {
            const int rr = m0 + wm0 + im * 16 + (lane >> 2) + half * 8;
            if (rr < cnt) {
                float* crow = Cbase + (size_t)rr * N + n0;
                #pragma unroll
                for (int jn = 0; jn < 4; jn++) {
                    const int col = wn0 + jn * 8 + (lane & 3) * 2;
                    float v0 = acc[im][jn][half * 2 + 0] + bp[col];
                    float v1 = acc[im][jn][half * 2 + 1] + bp[col + 1];
                    if (doRelu) { v0 = fmaxf(v0, 0.f); v1 = fmaxf(v1, 0.f); }
                    *(float2*)(crow + col) = make_float2(v0, v1);
                }
            }
        }
    }
}

// ---------------- routing ----------------
__global__ void route_kernel(const float* __restrict__ h2,
                             const float* __restrict__ G3,
                             const float* __restrict__ g3,
                             float* __restrict__ pout)
{
    const int gw   = (blockIdx.x * blockDim.x + threadIdx.x) >> 5;
    const int lane = threadIdx.x & 31;
    if (gw >= NTOK) return;

    const float* hrow = h2 + (size_t)gw * DIN;
    float acc[8] = {0,0,0,0,0,0,0,0};
    for (int k = lane; k < DIN; k += 32) {
        float hv = hrow[k];
        const float4 ga = *(const float4*)(G3 + k * 8);
        const float4 gb = *(const float4*)(G3 + k * 8 + 4);
        acc[0] += hv * ga.x; acc[1] += hv * ga.y;
        acc[2] += hv * ga.z; acc[3] += hv * ga.w;
        acc[4] += hv * gb.x; acc[5] += hv * gb.y;
        acc[6] += hv * gb.z; acc[7] += hv * gb.w;
    }
    #pragma unroll
    for (int e = 0; e < 8; e++)
        #pragma unroll
        for (int o = 16; o; o >>= 1)
            acc[e] += __shfl_xor_sync(0xffffffffu, acc[e], o);

    if (lane == 0) {
        float lg[8];
        #pragma unroll
        for (int e = 0; e < 8; e++) lg[e] = acc[e] + g3[e];

        int i1 = 0; float v1 = lg[0];
        #pragma unroll
        for (int e = 1; e < 8; e++)
            if (lg[e] > v1) { v1 = lg[e]; i1 = e; }
        int i2 = -1; float v2 = -3.4e38f;
        #pragma unroll
        for (int e = 0; e < 8; e++)
            if (e != i1 && lg[e] > v2) { v2 = lg[e]; i2 = e; }

        float ex = expf(v2 - v1);
        float p1 = 1.f / (1.f + ex);
        float p2 = ex  / (1.f + ex);

        float pr[8] = {0,0,0,0,0,0,0,0};
        pr[i1] = p1; pr[i2] = p2;
        float* prow = pout + (size_t)gw * NEXP;
        *(float4*)prow       = make_float4(pr[0], pr[1], pr[2], pr[3]);
        *(float4*)(prow + 4) = make_float4(pr[4], pr[5], pr[6], pr[7]);

        int s1 = atomicAdd(&g_cnt[i1], 1);
        g_list[i1 * NTOK + s1] = gw;
        g_slot[gw * 2 + 0] = i1 * NTOK + s1;
        g_wt  [gw * 2 + 0] = p1;
        int s2 = atomicAdd(&g_cnt[i2], 1);
        g_list[i2 * NTOK + s2] = gw;
        g_slot[gw * 2 + 1] = i2 * NTOK + s2;
        g_wt  [gw * 2 + 1] = p2;
    }
}

// ---------------- combine ----------------
__global__ void combine_kernel(float* __restrict__ y)
{
    const int t = blockIdx.x;
    const int c = threadIdx.x * 4;
    const int s0 = g_slot[t * 2 + 0];
    const int s1 = g_slot[t * 2 + 1];
    const float w0 = g_wt[t * 2 + 0];
    const float w1 = g_wt[t * 2 + 1];
    float4 a = *(const float4*)(g_pout + (size_t)s0 * OUTD + c);
    float4 b = *(const float4*)(g_pout + (size_t)s1 * OUTD + c);
    float4 rr;
    rr.x = w0 * a.x + w1 * b.x;
    rr.y = w0 * a.y + w1 * b.y;
    rr.z = w0 * a.z + w1 * b.z;
    rr.w = w0 * a.w + w1 * b.w;
    *(float4*)(y + (size_t)t * OUTD + c) = rr;
}

// ---------------- launch ----------------
extern "C" void kernel_launch(void* const* d_in, const int* in_sizes, int n_in,
                              void* d_out, int out_size)
{
    const float* x  = (const float*)d_in[0];
    const float* W1 = (const float*)d_in[1];
    const float* b1 = (const float*)d_in[2];
    const float* W2 = (const float*)d_in[3];
    const float* b2 = (const float*)d_in[4];
    const float* G1 = (const float*)d_in[5];
    const float* g1 = (const float*)d_in[6];
    const float* G2 = (const float*)d_in[7];
    const float* g2 = (const float*)d_in[8];
    const float* G3 = (const float*)d_in[9];
    const float* g3 = (const float*)d_in[10];

    float* y = (float*)d_out;
    float* p = (float*)d_out + (size_t)NTOK * OUTD;

    void* tmp;
    cudaGetSymbolAddress(&tmp, g_h1);   float* h1  = (float*)tmp;
    cudaGetSymbolAddress(&tmp, g_h2);   float* h2  = (float*)tmp;
    cudaGetSymbolAddress(&tmp, g_hid);  float* hid = (float*)tmp;
    cudaGetSymbolAddress(&tmp, g_pout); float* po  = (float*)tmp;
    cudaGetSymbolAddress(&tmp, g_list); int*   lst = (int*)tmp;
    cudaGetSymbolAddress(&tmp, g_cnt);  int*   cnt = (int*)tmp;

    const int smem2 = 2 * 2 * (A_PLB + B_PLB);   // NS=2 stages
    const int smem3 = 2 * 3 * (A_PLB + B_PLB);   // NS=3 stages
    cudaFuncSetAttribute(gemm_tc<2>, cudaFuncAttributeMaxDynamicSharedMemorySize, smem2);
    cudaFuncSetAttribute(gemm_tc<3>, cudaFuncAttributeMaxDynamicSharedMemorySize, smem3);

    reset_kernel<<<1, 32>>>();

    // gate layer 1: h1 = relu(x @ G1 + g1)   — bf16 3-split (selection-critical, err ~2^-23)
    gemm_tc<3><<<dim3(GH / 128, NTOK / 128, 1), 256, smem3>>>(
        x, 0, G1, 0, g1, 0, h1, 0, DIN, GH, 1, nullptr, nullptr);
    // gate layer 2: h2 = relu(h1 @ G2 + g2)  — bf16 3-split
    gemm_tc<3><<<dim3(DIN / 128, NTOK / 128, 1), 256, smem3>>>(
        h1, 0, G2, 0, g2, 0, h2, 0, GH, DIN, 1, nullptr, nullptr);
    // routing
    route_kernel<<<NTOK / 8, 256>>>(h2, G3, g3, p);
    // expert FFN1: hid = relu(x[list] @ W1[e] + b1[e])  — bf16 2-split
    gemm_tc<2><<<dim3(HID / 128, NTOK / 128, NEXP), 256, smem2>>>(
        x, 0, W1, (size_t)DIN * HID, b1, HID, hid, (size_t)NTOK * HID,
        DIN, HID, 1, lst, cnt);
    // expert FFN2: pout = hid @ W2[e] + b2[e]  — bf16 2-split
    gemm_tc<2><<<dim3(OUTD / 128, NTOK / 128, NEXP), 256, smem2>>>(
        hid, (size_t)NTOK * HID, W2, (size_t)HID * OUTD, b2, OUTD, po, (size_t)NTOK * OUTD,
        HID, OUTD, 0, nullptr, cnt);
    // combine
    combine_kernel<<<NTOK, 256>>>(y);
}